// round 10
// baseline (speedup 1.0000x reference)
#include <cuda_runtime.h>
#include <cstdint>

// ConditionalCNF via warp-level mma.sync (m16n8k8, tf32, single-pass).
// R9->R10: 16 samples/warp (mt=1) to halve accumulator registers and raise
// occupancy 4->6 CTAs/SM. Per-sample math identical to R9.
//
//   lane: q = lane>>2, c4 = lane&3
//   thread rows {q, q+8}; k-cols {c4+4e+8kt}
//   D cols per thread: {2c4, 2c4+1} + 8nt

using u32 = unsigned int;
using ull = unsigned long long;

static constexpr int NSTEPS = 20;
static constexpr int BLK = 128;

__device__ __forceinline__ float tanh_approx(float x) {
    float y; asm("tanh.approx.f32 %0, %1;" : "=f"(y) : "f"(x)); return y;
}
__device__ __forceinline__ ull pack2(float lo, float hi) {
    ull r; asm("mov.b64 %0, {%1, %2};" : "=l"(r) : "f"(lo), "f"(hi)); return r;
}
__device__ __forceinline__ void unpack2(ull v, float& lo, float& hi) {
    asm("mov.b64 {%0, %1}, %2;" : "=f"(lo), "=f"(hi) : "l"(v));
}
__device__ __forceinline__ void unpack2u(ull v, u32& lo, u32& hi) {
    asm("mov.b64 {%0, %1}, %2;" : "=r"(lo), "=r"(hi) : "l"(v));
}
__device__ __forceinline__ ull fma2o(ull a, ull b, ull c) {
    ull d; asm("fma.rn.f32x2 %0, %1, %2, %3;" : "=l"(d) : "l"(a), "l"(b), "l"(c));
    return d;
}
__device__ __forceinline__ ull mul2(ull a, ull b) {
    ull d; asm("mul.rn.f32x2 %0, %1, %2;" : "=l"(d) : "l"(a), "l"(b));
    return d;
}
__device__ __forceinline__ u32 tf32_rna(float x) {
    u32 r; asm("cvt.rna.tf32.f32 %0, %1;" : "=r"(r) : "f"(x)); return r;
}
__device__ __forceinline__ void mma_tf32(float& c0, float& c1, float& c2, float& c3,
                                         u32 a0, u32 a1, u32 a2, u32 a3,
                                         u32 b0, u32 b1) {
    asm volatile("mma.sync.aligned.m16n8k8.row.col.f32.tf32.tf32.f32 "
                 "{%0,%1,%2,%3}, {%4,%5,%6,%7}, {%8,%9}, {%0,%1,%2,%3};"
                 : "+f"(c0), "+f"(c1), "+f"(c2), "+f"(c3)
                 : "r"(a0), "r"(a1), "r"(a2), "r"(a3), "r"(b0), "r"(b1));
}

__global__ void __launch_bounds__(BLK, 6)
cnf_kernel(const float* __restrict__ T,
           const float* __restrict__ cond,
           const float* __restrict__ gW1,
           const float* __restrict__ gb1,
           const float* __restrict__ gW2,
           const float* __restrict__ gb2,
           const float* __restrict__ gW3,
           const float* __restrict__ gb3,
           float* __restrict__ out,
           int B)
{
    __shared__ ull spre1[8 * BLK];    // layer1 preact pairs [slot][tid] (8 KB)
    __shared__ ull sB   [16 * 32];    // W2 tf32 B-frags [tile][lane]    (4 KB)
    __shared__ ull sw10p[16];         // {w10[k0], w10[k1]} per (kt,c4)
    __shared__ ull snw10p[16];
    __shared__ ull sb2p [16];         // {b2[n0], b2[n0+1]} per (nt,c4)
    __shared__ ull sw3p [16];

    const int tid = threadIdx.x;
    const int ln  = tid & 31;
    const int wid = tid >> 5;
    const int q   = ln >> 2;
    const int c4  = ln & 3;

    // ---- one-time smem init ----
    for (int e = tid; e < 16 * 32; e += BLK) {
        int t = e >> 5, l = e & 31;
        int kt = t >> 2, nt = t & 3;
        int n  = (l >> 2) + 8 * nt;
        int k0 = (l & 3) + 8 * kt;
        u32 b0 = tf32_rna(gW2[n * 32 + k0]);
        u32 b1 = tf32_rna(gW2[n * 32 + k0 + 4]);
        sB[e] = ((ull)b1 << 32) | b0;
    }
    if (tid < 16) {
        int kt = tid >> 2, cc = tid & 3;
        float w0 = gW1[(cc + 8 * kt) * 9];
        float w1 = gW1[(cc + 4 + 8 * kt) * 9];
        sw10p[tid]  = pack2(w0, w1);
        snw10p[tid] = pack2(-w0, -w1);
        int nt = tid >> 2;
        int n0 = 2 * cc + 8 * nt;
        sb2p[tid] = pack2(gb2[n0], gb2[n0 + 1]);
        sw3p[tid] = pack2(gW3[n0], gW3[n0 + 1]);
    }

    // ---- per-thread setup: RK state + pre1 into smem ----
    const int gwbase = blockIdx.x * 64 + wid * 16;   // 16 samples per warp
    float z[2], logp[2];
#pragma unroll
    for (int rs = 0; rs < 2; rs++) {
        int s = gwbase + q + 8 * rs;
        z[rs] = __ldg(T + s);
        logp[rs] = 0.0f;
        const float4* cp = reinterpret_cast<const float4*>(cond) + s * 2;
        float4 ca = __ldg(cp), cb = __ldg(cp + 1);
        float cc[8] = {ca.x, ca.y, ca.z, ca.w, cb.x, cb.y, cb.z, cb.w};
#pragma unroll
        for (int kt = 0; kt < 4; kt++) {
            int k0 = c4 + 8 * kt, k1 = k0 + 4;
            float p0 = __ldg(gb1 + k0), p1 = __ldg(gb1 + k1);
#pragma unroll
            for (int c = 0; c < 8; c++) {
                p0 = fmaf(cc[c], __ldg(gW1 + k0 * 9 + 1 + c), p0);
                p1 = fmaf(cc[c], __ldg(gW1 + k1 * 9 + 1 + c), p1);
            }
            spre1[(rs * 4 + kt) * BLK + tid] = pack2(p0, p1);
        }
    }
    const float b3v = __ldg(gb3);
    __syncthreads();

    const float dt  = 1.0f / (float)NSTEPS;
    const float dt6 = dt / 6.0f;

#pragma unroll 1
    for (int step = 0; step < NSTEPS; step++) {
        float zs[2], az[2], ad2[2];
#pragma unroll
        for (int rs = 0; rs < 2; rs++) { zs[rs] = z[rs]; az[rs] = 0.0f; ad2[rs] = 0.0f; }

#pragma unroll 1
        for (int st = 0; st < 4; st++) {
            float accS[16], accT[16];
#pragma unroll
            for (int i = 0; i < 16; i++) { accS[i] = 0.0f; accT[i] = 0.0f; }

            ull zzp[2];
#pragma unroll
            for (int rs = 0; rs < 2; rs++) zzp[rs] = pack2(zs[rs], zs[rs]);

            // ---- fused layer1 + dual matvec over kt ----
#pragma unroll
            for (int kt = 0; kt < 4; kt++) {
                ull wp  = sw10p[kt * 4 + c4];
                ull nwp = snw10p[kt * 4 + c4];
                u32 ah[2][2], adf[2][2];
#pragma unroll
                for (int rs = 0; rs < 2; rs++) {
                    ull xp = fma2o(zzp[rs], wp, spre1[(rs * 4 + kt) * BLK + tid]);
                    float x0, x1; unpack2(xp, x0, x1);
                    float h0 = tanh_approx(x0);
                    float h1 = tanh_approx(x1);
                    ull hp = pack2(h0, h1);
                    ull hh = mul2(hp, hp);
                    ull dp = fma2o(hh, nwp, wp);        // (1-h^2)*w10
                    ah[rs][0] = __float_as_uint(h0);
                    ah[rs][1] = __float_as_uint(h1);
                    unpack2u(dp, adf[rs][0], adf[rs][1]);
                }
#pragma unroll
                for (int nt = 0; nt < 4; nt++) {
                    u32 b0, b1;
                    unpack2u(sB[(kt * 4 + nt) * 32 + ln], b0, b1);
                    int ba = nt * 4;
                    mma_tf32(accS[ba], accS[ba+1], accS[ba+2], accS[ba+3],
                             ah[0][0], ah[1][0], ah[0][1], ah[1][1], b0, b1);
                    mma_tf32(accT[ba], accT[ba+1], accT[ba+2], accT[ba+3],
                             adf[0][0], adf[1][0], adf[0][1], adf[1][1], b0, b1);
                }
            }

            // ---- merged epilogue: dz, dv per cell ----
            float dzp[2] = {0.f, 0.f};
            float dvp[2] = {0.f, 0.f};
#pragma unroll
            for (int nt = 0; nt < 4; nt++) {
                float blo, bhi; unpack2(sb2p[nt * 4 + c4], blo, bhi);
                float wlo, whi; unpack2(sw3p[nt * 4 + c4], wlo, whi);
                int ba = nt * 4;
                float h2, g;
                h2 = tanh_approx(accS[ba + 0] + blo);
                dzp[0] = fmaf(wlo, h2, dzp[0]);
                g = fmaf(-h2, h2, 1.0f) * wlo;
                dvp[0] = fmaf(g, accT[ba + 0], dvp[0]);
                h2 = tanh_approx(accS[ba + 1] + bhi);
                dzp[0] = fmaf(whi, h2, dzp[0]);
                g = fmaf(-h2, h2, 1.0f) * whi;
                dvp[0] = fmaf(g, accT[ba + 1], dvp[0]);
                h2 = tanh_approx(accS[ba + 2] + blo);
                dzp[1] = fmaf(wlo, h2, dzp[1]);
                g = fmaf(-h2, h2, 1.0f) * wlo;
                dvp[1] = fmaf(g, accT[ba + 2], dvp[1]);
                h2 = tanh_approx(accS[ba + 3] + bhi);
                dzp[1] = fmaf(whi, h2, dzp[1]);
                g = fmaf(-h2, h2, 1.0f) * whi;
                dvp[1] = fmaf(g, accT[ba + 3], dvp[1]);
            }

            // ---- quad reduction + RK accumulate ----
            const float coef = (st == 1 || st == 2) ? 2.0f : 1.0f;
            const float a = (st == 2) ? dt : (0.5f * dt);
#pragma unroll
            for (int rs = 0; rs < 2; rs++) {
                float dz = dzp[rs], dv = dvp[rs];
                dz += __shfl_xor_sync(0xffffffffu, dz, 1);
                dz += __shfl_xor_sync(0xffffffffu, dz, 2);
                dv += __shfl_xor_sync(0xffffffffu, dv, 1);
                dv += __shfl_xor_sync(0xffffffffu, dv, 2);
                float kz = dz + b3v;
                az[rs]  = fmaf(coef, kz, az[rs]);
                ad2[rs] = fmaf(coef, dv, ad2[rs]);
                zs[rs]  = fmaf(a, kz, z[rs]);
            }
        }

#pragma unroll
        for (int rs = 0; rs < 2; rs++) {
            z[rs]    = fmaf(dt6, az[rs],  z[rs]);
            logp[rs] = fmaf(dt6, ad2[rs], logp[rs]);
        }
    }

    if (c4 == 0) {
#pragma unroll
        for (int rs = 0; rs < 2; rs++) {
            int s = gwbase + q + 8 * rs;
            out[s]     = z[rs];
            out[B + s] = logp[rs];
        }
    }
}

extern "C" void kernel_launch(void* const* d_in, const int* in_sizes, int n_in,
                              void* d_out, int out_size) {
    const float* T    = (const float*)d_in[0];
    const float* cond = (const float*)d_in[1];
    const float* W1   = (const float*)d_in[2];
    const float* b1   = (const float*)d_in[3];
    const float* W2   = (const float*)d_in[4];
    const float* b2   = (const float*)d_in[5];
    const float* W3   = (const float*)d_in[6];
    const float* b3   = (const float*)d_in[7];
    float* out = (float*)d_out;

    const int B = in_sizes[0];
    const int blocks = (B + 63) / 64;   // 64 samples per CTA (16 per warp)
    cnf_kernel<<<blocks, BLK>>>(T, cond, W1, b1, W2, b2, W3, b3, out, B);
}